// round 7
// baseline (speedup 1.0000x reference)
#include <cuda_runtime.h>

#define NROWS 16384
#define DCOLS 2048
#define TPB   256
#define GRID  1024                       // 8 warps/CTA * 1024 = 8192 warps
#define WARPS_TOTAL (GRID * 8)           // each warp handles exactly 2 rows

// Device-global scratch (no allocations allowed).
__device__ float        g_partial[GRID];
__device__ unsigned int g_counter = 0;   // waiter resets -> replay-safe

__device__ __forceinline__ void red_release_add(unsigned int* p, unsigned int v) {
    asm volatile("red.release.gpu.global.add.u32 [%0], %1;" :: "l"(p), "r"(v) : "memory");
}
__device__ __forceinline__ unsigned int ld_acquire(const unsigned int* p) {
    unsigned int v;
    asm volatile("ld.acquire.gpu.global.u32 %0, [%1];" : "=r"(v) : "l"(p) : "memory");
    return v;
}

__global__ void __launch_bounds__(TPB) cosine_loss_persistent(
    const float* __restrict__ cxr, const float* __restrict__ ehr,
    float* __restrict__ out)
{
    const int t    = threadIdx.x;
    const int lane = t & 31;
    const int warp = t >> 5;
    __shared__ float swarp[8];

    if (blockIdx.x < GRID) {
        // ── Worker: warp-per-row, exactly 2 rows per warp, single wave ──
        const int gw = blockIdx.x * 8 + warp;   // 0..8191
        float csum = 0.f;

        #pragma unroll 1                         // REAL loop: keeps regs at 32
        for (int row = gw; row < NROWS; row += WARPS_TOTAL) {
            const float4* __restrict__ a = reinterpret_cast<const float4*>(ehr + (size_t)row * DCOLS);
            const float4* __restrict__ b = reinterpret_cast<const float4*>(cxr + (size_t)row * DCOLS);

            float dot = 0.f, na = 0.f, nb = 0.f;

            // 512 float4 per tensor per row; 32 lanes -> 16 float4 each.
            // 8 chunks, 4 streaming loads front-batched per chunk (MLP=4).
            #pragma unroll
            for (int c = 0; c < 8; c++) {
                float4 a0 = __ldcs(&a[lane + 64 * c]);
                float4 b0 = __ldcs(&b[lane + 64 * c]);
                float4 a1 = __ldcs(&a[lane + 64 * c + 32]);
                float4 b1 = __ldcs(&b[lane + 64 * c + 32]);

                dot += a0.x*b0.x + a0.y*b0.y + a0.z*b0.z + a0.w*b0.w;
                na  += a0.x*a0.x + a0.y*a0.y + a0.z*a0.z + a0.w*a0.w;
                nb  += b0.x*b0.x + b0.y*b0.y + b0.z*b0.z + b0.w*b0.w;

                dot += a1.x*b1.x + a1.y*b1.y + a1.z*b1.z + a1.w*b1.w;
                na  += a1.x*a1.x + a1.y*a1.y + a1.z*a1.z + a1.w*a1.w;
                nb  += b1.x*b1.x + b1.y*b1.y + b1.z*b1.z + b1.w*b1.w;
            }

            #pragma unroll
            for (int o = 16; o > 0; o >>= 1) {
                dot += __shfl_xor_sync(0xffffffffu, dot, o);
                na  += __shfl_xor_sync(0xffffffffu, na,  o);
                nb  += __shfl_xor_sync(0xffffffffu, nb,  o);
            }

            csum += dot * rsqrtf(na * nb);
        }

        // ── Per-CTA publish: one smem reduce + one release-RED ──
        if (lane == 0) swarp[warp] = csum;
        __syncthreads();

        if (t == 0) {
            float bs = 0.f;
            #pragma unroll
            for (int i = 0; i < 8; i++) bs += swarp[i];
            g_partial[blockIdx.x] = bs;
            red_release_add(&g_counter, 1u);    // fire-and-forget
        }
        return;
    }

    // ── Waiter CTA (blockIdx.x == GRID): spin, then 4 KB final reduce ──
    if (t == 0) {
        while (ld_acquire(&g_counter) != (unsigned)GRID)
            __nanosleep(64);
    }
    __syncthreads();

    // 1024 partials over 256 threads -> 4 each, batched; L2-resident.
    float s = __ldcg(&g_partial[t])
            + __ldcg(&g_partial[t +     TPB])
            + __ldcg(&g_partial[t + 2 * TPB])
            + __ldcg(&g_partial[t + 3 * TPB]);

    #pragma unroll
    for (int o = 16; o > 0; o >>= 1)
        s += __shfl_xor_sync(0xffffffffu, s, o);

    if (lane == 0) swarp[warp] = s;
    __syncthreads();

    if (t == 0) {
        float tot = 0.f;
        #pragma unroll
        for (int i = 0; i < 8; i++) tot += swarp[i];
        out[0] = 1.0f - tot / (float)NROWS;
        __threadfence();
        g_counter = 0;                           // reset for next graph replay
    }
}

extern "C" void kernel_launch(void* const* d_in, const int* in_sizes, int n_in,
                              void* d_out, int out_size)
{
    const float* cxr = (const float*)d_in[0];
    const float* ehr = (const float*)d_in[1];
    float* out = (float*)d_out;
    cosine_loss_persistent<<<GRID + 1, TPB>>>(cxr, ehr, out);
}

// round 8
// speedup vs baseline: 1.0923x; 1.0923x over previous
#include <cuda_runtime.h>

#define NROWS 16384
#define DCOLS 2048
#define TPB   256
#define GRID  1024                        // 8 warps/CTA * 1024 = 8192 warps
#define WARPS_TOTAL (GRID * 8)            // each warp: exactly 2 rows, no idle phase

// Device-global scratch (no allocations allowed).
__device__ float        g_partial[GRID];
__device__ unsigned int g_counter = 0;    // waiter resets -> replay-safe

__device__ __forceinline__ void red_release_add(unsigned int* p, unsigned int v) {
    asm volatile("red.release.gpu.global.add.u32 [%0], %1;" :: "l"(p), "r"(v) : "memory");
}
__device__ __forceinline__ unsigned int ld_acquire(const unsigned int* p) {
    unsigned int v;
    asm volatile("ld.acquire.gpu.global.u32 %0, [%1];" : "=r"(v) : "l"(p) : "memory");
    return v;
}

// minBlocksPerMultiprocessor=8 forces ptxas to a <=32-reg allocation.
__global__ void __launch_bounds__(TPB, 8) cosine_loss_persistent(
    const float* __restrict__ cxr, const float* __restrict__ ehr,
    float* __restrict__ out)
{
    const int t    = threadIdx.x;
    const int lane = t & 31;
    const int warp = t >> 5;
    __shared__ float swarp[8];

    if (blockIdx.x < GRID) {
        const int gw = blockIdx.x * 8 + warp;            // 0..8191
        // Fold lane into base pointers ONCE; advance by constant stride per row.
        const float4* a = reinterpret_cast<const float4*>(ehr) + (size_t)gw * (DCOLS / 4) + lane;
        const float4* b = reinterpret_cast<const float4*>(cxr) + (size_t)gw * (DCOLS / 4) + lane;
        const size_t row_stride = (size_t)WARPS_TOTAL * (DCOLS / 4);

        float csum = 0.f;

        #pragma unroll 1
        for (int r = 0; r < 2; r++) {
            float dot = 0.f, na = 0.f, nb = 0.f;

            // 512 float4 per tensor per row; 32 lanes -> 16 float4 each.
            // 8 chunks, 4 streaming loads front-batched per chunk (MLP=4).
            #pragma unroll
            for (int c = 0; c < 8; c++) {
                float4 a0 = __ldcs(a + 64 * c);
                float4 b0 = __ldcs(b + 64 * c);
                float4 a1 = __ldcs(a + 64 * c + 32);
                float4 b1 = __ldcs(b + 64 * c + 32);

                dot += a0.x*b0.x + a0.y*b0.y + a0.z*b0.z + a0.w*b0.w;
                na  += a0.x*a0.x + a0.y*a0.y + a0.z*a0.z + a0.w*a0.w;
                nb  += b0.x*b0.x + b0.y*b0.y + b0.z*b0.z + b0.w*b0.w;

                dot += a1.x*b1.x + a1.y*b1.y + a1.z*b1.z + a1.w*b1.w;
                na  += a1.x*a1.x + a1.y*a1.y + a1.z*a1.z + a1.w*a1.w;
                nb  += b1.x*b1.x + b1.y*b1.y + b1.z*b1.z + b1.w*b1.w;
            }

            #pragma unroll
            for (int o = 16; o > 0; o >>= 1) {
                dot += __shfl_xor_sync(0xffffffffu, dot, o);
                na  += __shfl_xor_sync(0xffffffffu, na,  o);
                nb  += __shfl_xor_sync(0xffffffffu, nb,  o);
            }

            csum += dot * rsqrtf(na * nb);
            a += row_stride;
            b += row_stride;
        }

        // ── Per-CTA publish: one smem reduce + one release-RED ──
        if (lane == 0) swarp[warp] = csum;
        __syncthreads();

        if (t == 0) {
            float bs = 0.f;
            #pragma unroll
            for (int i = 0; i < 8; i++) bs += swarp[i];
            g_partial[blockIdx.x] = bs;
            red_release_add(&g_counter, 1u);             // fire-and-forget
        }
        return;
    }

    // ── Waiter CTA (blockIdx.x == GRID): spin, then 4 KB final reduce ──
    if (t == 0) {
        while (ld_acquire(&g_counter) != (unsigned)GRID)
            __nanosleep(64);
    }
    __syncthreads();

    float s = __ldcg(&g_partial[t])
            + __ldcg(&g_partial[t +     TPB])
            + __ldcg(&g_partial[t + 2 * TPB])
            + __ldcg(&g_partial[t + 3 * TPB]);

    #pragma unroll
    for (int o = 16; o > 0; o >>= 1)
        s += __shfl_xor_sync(0xffffffffu, s, o);

    if (lane == 0) swarp[warp] = s;
    __syncthreads();

    if (t == 0) {
        float tot = 0.f;
        #pragma unroll
        for (int i = 0; i < 8; i++) tot += swarp[i];
        out[0] = 1.0f - tot / (float)NROWS;
        __threadfence();
        g_counter = 0;                                   // reset for replay
    }
}

extern "C" void kernel_launch(void* const* d_in, const int* in_sizes, int n_in,
                              void* d_out, int out_size)
{
    const float* cxr = (const float*)d_in[0];
    const float* ehr = (const float*)d_in[1];
    float* out = (float*)d_out;
    cosine_loss_persistent<<<GRID + 1, TPB>>>(cxr, ehr, out);
}

// round 10
// speedup vs baseline: 1.1309x; 1.0353x over previous
#include <cuda_runtime.h>

#define NROWS 16384
#define DCOLS 2048
#define TPB   256
#define RPB   2                         // rows per block (contiguous pair)
#define GRID  (NROWS / RPB)             // 8192 worker CTAs + 1 waiter

// Device-global scratch (no allocations allowed).
__device__ float        g_partial[GRID];
__device__ unsigned int g_counter = 0;  // waiter resets -> replay-safe

__device__ __forceinline__ void red_release_add(unsigned int* p, unsigned int v) {
    asm volatile("red.release.gpu.global.add.u32 [%0], %1;" :: "l"(p), "r"(v) : "memory");
}
__device__ __forceinline__ unsigned int ld_acquire(const unsigned int* p) {
    unsigned int v;
    asm volatile("ld.acquire.gpu.global.u32 %0, [%1];" : "=r"(v) : "l"(p) : "memory");
    return v;
}

__global__ void __launch_bounds__(TPB, 8) cosine_loss_kernel(
    const float* __restrict__ cxr, const float* __restrict__ ehr,
    float* __restrict__ out)
{
    const int t    = threadIdx.x;
    const int lane = t & 31;
    const int warp = t >> 5;
    __shared__ float sdot[8], sna[8], snb[8];

    if (blockIdx.x < GRID) {
        // ── Worker: two CONSECUTIVE rows per block (16 KB contiguous/tensor) ──
        // Fold thread offset into base pointers once; advance by one row.
        const float4* a = reinterpret_cast<const float4*>(ehr)
                        + (size_t)blockIdx.x * RPB * (DCOLS / 4) + t;
        const float4* b = reinterpret_cast<const float4*>(cxr)
                        + (size_t)blockIdx.x * RPB * (DCOLS / 4) + t;
        float csum = 0.f;   // thread 0 accumulates cos over both rows

        #pragma unroll 1
        for (int r = 0; r < RPB; r++) {
            // R6 mainloop: 512 float4/tensor, 256 threads -> 2 each,
            // 4 streaming loads front-batched (MLP=4).
            float4 a0 = __ldcs(a);
            float4 b0 = __ldcs(b);
            float4 a1 = __ldcs(a + TPB);
            float4 b1 = __ldcs(b + TPB);

            float dot, na, nb;
            dot  = a0.x*b0.x + a0.y*b0.y + a0.z*b0.z + a0.w*b0.w;
            na   = a0.x*a0.x + a0.y*a0.y + a0.z*a0.z + a0.w*a0.w;
            nb   = b0.x*b0.x + b0.y*b0.y + b0.z*b0.z + b0.w*b0.w;
            dot += a1.x*b1.x + a1.y*b1.y + a1.z*b1.z + a1.w*b1.w;
            na  += a1.x*a1.x + a1.y*a1.y + a1.z*a1.z + a1.w*a1.w;
            nb  += b1.x*b1.x + b1.y*b1.y + b1.z*b1.z + b1.w*b1.w;

            #pragma unroll
            for (int o = 16; o > 0; o >>= 1) {
                dot += __shfl_xor_sync(0xffffffffu, dot, o);
                na  += __shfl_xor_sync(0xffffffffu, na,  o);
                nb  += __shfl_xor_sync(0xffffffffu, nb,  o);
            }

            if (lane == 0) { sdot[warp] = dot; sna[warp] = na; snb[warp] = nb; }
            __syncthreads();

            if (t == 0) {
                float d = 0.f, x = 0.f, y = 0.f;
                #pragma unroll
                for (int i = 0; i < 8; i++) { d += sdot[i]; x += sna[i]; y += snb[i]; }
                csum += d * rsqrtf(x * y);
            }
            __syncthreads();            // smem safe for next row

            a += DCOLS / 4;             // next consecutive row
            b += DCOLS / 4;
        }

        if (t == 0) {
            g_partial[blockIdx.x] = csum;
            red_release_add(&g_counter, 1u);   // fire-and-forget publish
        }
        return;                                 // CTA retires immediately
    }

    // ── Waiter CTA (blockIdx.x == GRID): spin, then 32 KB final reduce ──
    if (t == 0) {
        while (ld_acquire(&g_counter) != (unsigned)GRID)
            __nanosleep(64);
    }
    __syncthreads();

    const float4* rp = reinterpret_cast<const float4*>(g_partial);
    float s = 0.f;
    // 2048 float4 over 256 threads -> 8 each, 4-deep batches; L2-resident.
    #pragma unroll
    for (int i = 0; i < 2; i++) {
        float4 v0 = __ldcg(&rp[t + (4*i + 0) * TPB]);
        float4 v1 = __ldcg(&rp[t + (4*i + 1) * TPB]);
        float4 v2 = __ldcg(&rp[t + (4*i + 2) * TPB]);
        float4 v3 = __ldcg(&rp[t + (4*i + 3) * TPB]);
        s += v0.x + v0.y + v0.z + v0.w;
        s += v1.x + v1.y + v1.z + v1.w;
        s += v2.x + v2.y + v2.z + v2.w;
        s += v3.x + v3.y + v3.z + v3.w;
    }

    #pragma unroll
    for (int o = 16; o > 0; o >>= 1)
        s += __shfl_xor_sync(0xffffffffu, s, o);

    if (lane == 0) sdot[warp] = s;
    __syncthreads();

    if (t == 0) {
        float tot = 0.f;
        #pragma unroll
        for (int i = 0; i < 8; i++) tot += sdot[i];
        out[0] = 1.0f - tot / (float)NROWS;
        __threadfence();
        g_counter = 0;                          // reset for next graph replay
    }
}

extern "C" void kernel_launch(void* const* d_in, const int* in_sizes, int n_in,
                              void* d_out, int out_size)
{
    const float* cxr = (const float*)d_in[0];
    const float* ehr = (const float*)d_in[1];
    float* out = (float*)d_out;
    cosine_loss_kernel<<<GRID + 1, TPB>>>(cxr, ehr, out);
}